// round 1
// baseline (speedup 1.0000x reference)
#include <cuda_runtime.h>
#include <math.h>

#define MROWS 8192
#define DDIM  1024
#define FDIM  4096

// ---------------- scratch (static device globals; no allocations) ----------
__device__ float g_xn  [MROWS*DDIM];
__device__ float g_q   [MROWS*DDIM];
__device__ float g_k   [MROWS*DDIM];
__device__ float g_v   [MROWS*DDIM];
__device__ float g_ao  [MROWS*DDIM];
__device__ float g_attn[MROWS*DDIM];
__device__ float g_h1  [MROWS*FDIM];
__device__ float g_wot [DDIM*DDIM];
__device__ float g_qs  [64];

// ---------------- per-dim q scale: (log2e/sqrt(H)) * softplus(p) ----------
__global__ void qscale_kernel(const float* __restrict__ p, float* __restrict__ s) {
    int h = threadIdx.x;
    if (h < 64) {
        float x  = p[h];
        float sp = (x > 20.f) ? x : log1pf(expf(x));
        s[h] = (1.442695041f / 8.0f) * sp;
    }
}

// ---------------- RMSNorm: one block per row, 256 threads, float4 ----------
__global__ void rmsnorm_kernel(const float* __restrict__ x,
                               const float* __restrict__ scale,
                               float* __restrict__ y) {
    int row = blockIdx.x, tid = threadIdx.x;
    const float4* xr = (const float4*)(x + (long)row * DDIM);
    float4 xv = xr[tid];
    float ss = xv.x*xv.x + xv.y*xv.y + xv.z*xv.z + xv.w*xv.w;
    __shared__ float red[256];
    red[tid] = ss; __syncthreads();
    for (int o = 128; o > 0; o >>= 1) {
        if (tid < o) red[tid] += red[tid + o];
        __syncthreads();
    }
    float inv = rsqrtf(red[0] * (1.0f / DDIM) + 1e-6f);
    float4 sv = ((const float4*)scale)[tid];
    float4 r;
    r.x = xv.x * inv * sv.x; r.y = xv.y * inv * sv.y;
    r.z = xv.z * inv * sv.z; r.w = xv.w * inv * sv.w;
    ((float4*)(y + (long)row * DDIM))[tid] = r;
}

// ---------------- LayerNorm ----------
__global__ void layernorm_kernel(const float* __restrict__ x,
                                 const float* __restrict__ gamma,
                                 const float* __restrict__ beta,
                                 float* __restrict__ y) {
    int row = blockIdx.x, tid = threadIdx.x;
    const float4* xr = (const float4*)(x + (long)row * DDIM);
    float4 xv = xr[tid];
    float s1 = xv.x + xv.y + xv.z + xv.w;
    float s2 = xv.x*xv.x + xv.y*xv.y + xv.z*xv.z + xv.w*xv.w;
    __shared__ float r1[256], r2[256];
    r1[tid] = s1; r2[tid] = s2; __syncthreads();
    for (int o = 128; o > 0; o >>= 1) {
        if (tid < o) { r1[tid] += r1[tid + o]; r2[tid] += r2[tid + o]; }
        __syncthreads();
    }
    float mean = r1[0] * (1.0f / DDIM);
    float var  = r2[0] * (1.0f / DDIM) - mean * mean;
    float inv  = rsqrtf(var + 1e-5f);
    float4 gv = ((const float4*)gamma)[tid];
    float4 bv = ((const float4*)beta)[tid];
    float4 r;
    r.x = (xv.x - mean) * inv * gv.x + bv.x;
    r.y = (xv.y - mean) * inv * gv.y + bv.y;
    r.z = (xv.z - mean) * inv * gv.z + bv.z;
    r.w = (xv.w - mean) * inv * gv.w + bv.w;
    ((float4*)(y + (long)row * DDIM))[tid] = r;
}

// ---------------- 1024x1024 transpose (for wo) ----------
__global__ void transpose1024(const float* __restrict__ in, float* __restrict__ out) {
    __shared__ float t[32][33];
    int bx = blockIdx.x * 32, by = blockIdx.y * 32;
    int tx = threadIdx.x, ty = threadIdx.y;  // 32 x 8
    #pragma unroll
    for (int i = 0; i < 32; i += 8)
        t[ty + i][tx] = in[(long)(by + ty + i) * DDIM + bx + tx];
    __syncthreads();
    #pragma unroll
    for (int i = 0; i < 32; i += 8)
        out[(long)(bx + ty + i) * DDIM + by + tx] = t[tx][ty + i];
}

// ---------------- SGEMM: C[M,Nc] = A[M,K] @ B[K,Nc]  (+ epilogue) ----------
// mode 0: + bias
// mode 1: (+ bias) * colscale[col % 64]       (q scaling)
// mode 2: relu(+ bias)
// mode 3: + bias + Res[row, col]              (residual add)
__global__ __launch_bounds__(256, 2)
void sgemm128(const float* __restrict__ A, const float* __restrict__ B,
              const float* __restrict__ bias, const float* __restrict__ Res,
              const float* __restrict__ colscale, float* __restrict__ C,
              int M, int Nc, int K, int mode) {
    __shared__ float Ast[16][132];   // [k][m], padded
    __shared__ float Bs [16][128];   // [k][n]
    int tid = threadIdx.x;
    int tx = tid % 16, ty = tid / 16;
    long row0 = (long)blockIdx.y * 128, col0 = (long)blockIdx.x * 128;

    float acc[8][8];
    #pragma unroll
    for (int i = 0; i < 8; i++)
        #pragma unroll
        for (int j = 0; j < 8; j++) acc[i][j] = 0.f;

    int ar  = tid / 4;   // 0..63 (A tile row, + 64 second pass)
    int ac4 = tid % 4;   // A float4 col within 16
    int br  = tid / 16;  // 0..15 (B tile row)
    int bc4 = tid % 16;  // B float4 col

    const float* Aptr = A + (row0 + ar) * (long)K + ac4 * 4;
    const float* Bptr = B + (long)br * Nc + col0 + bc4 * 4;

    for (int kt = 0; kt < K; kt += 16) {
        float4 a0 = *(const float4*)(Aptr + kt);
        float4 a1 = *(const float4*)(Aptr + 64 * (long)K + kt);
        float4 b0 = *(const float4*)(Bptr + (long)kt * Nc);
        float4 b1 = *(const float4*)(Bptr + (long)kt * Nc + 64);
        int kc = ac4 * 4;
        Ast[kc+0][ar] = a0.x; Ast[kc+1][ar] = a0.y; Ast[kc+2][ar] = a0.z; Ast[kc+3][ar] = a0.w;
        Ast[kc+0][ar+64] = a1.x; Ast[kc+1][ar+64] = a1.y; Ast[kc+2][ar+64] = a1.z; Ast[kc+3][ar+64] = a1.w;
        *(float4*)&Bs[br][bc4*4]      = b0;
        *(float4*)&Bs[br][bc4*4 + 64] = b1;
        __syncthreads();
        #pragma unroll
        for (int k = 0; k < 16; k++) {
            float4 pa0 = *(const float4*)&Ast[k][ty*8];
            float4 pa1 = *(const float4*)&Ast[k][ty*8 + 4];
            float4 pb0 = *(const float4*)&Bs[k][tx*8];
            float4 pb1 = *(const float4*)&Bs[k][tx*8 + 4];
            float av[8] = {pa0.x,pa0.y,pa0.z,pa0.w,pa1.x,pa1.y,pa1.z,pa1.w};
            float bv[8] = {pb0.x,pb0.y,pb0.z,pb0.w,pb1.x,pb1.y,pb1.z,pb1.w};
            #pragma unroll
            for (int i = 0; i < 8; i++)
                #pragma unroll
                for (int j = 0; j < 8; j++)
                    acc[i][j] += av[i] * bv[j];
        }
        __syncthreads();
    }

    // epilogue
    #pragma unroll
    for (int i = 0; i < 8; i++) {
        long row = row0 + ty*8 + i;
        float* crow = C + row * Nc + col0 + tx*8;
        const float* rrow = (mode == 3) ? (Res + row * Nc + col0 + tx*8) : nullptr;
        #pragma unroll
        for (int j = 0; j < 8; j++) {
            long col = col0 + tx*8 + j;
            float v = acc[i][j] + bias[col];
            if (mode == 1)      v *= colscale[col & 63];
            else if (mode == 2) v = fmaxf(v, 0.f);
            else if (mode == 3) v += rrow[j];
            crow[j] = v;
        }
    }
}

// ---------------- causal flash attention ----------
// grid: (T/64, N, B); block 256.
// q,k,v: [B*T, N*H] fp32 (head n occupies cols n*64..n*64+63), q pre-scaled.
__global__ __launch_bounds__(256)
void attn_kernel(const float* __restrict__ q, const float* __restrict__ k,
                 const float* __restrict__ v, const float* __restrict__ pad,
                 float* __restrict__ out) {
    __shared__ float QsT[64*64];   // [h][r]
    __shared__ float KP [64*64];   // [h][s] for K, reused as P[s][r]
    __shared__ float Vs [64*64];   // [s][c]
    int tid = threadIdx.x;
    int qt = blockIdx.x, n = blockIdx.y, b = blockIdx.z;
    long base = (long)b * 1024 * 1024 + n * 64;

    // load Q tile transposed
    {
        int r = tid / 4, seg = tid % 4;
        const float* qp = q + base + (long)(qt*64 + r) * DDIM + seg*16;
        #pragma unroll
        for (int u = 0; u < 4; u++) {
            float4 t4 = *(const float4*)(qp + u*4);
            int h = seg*16 + u*4;
            QsT[(h+0)*64 + r] = t4.x; QsT[(h+1)*64 + r] = t4.y;
            QsT[(h+2)*64 + r] = t4.z; QsT[(h+3)*64 + r] = t4.w;
        }
    }
    int rr = (tid / 16) * 4;   // query row block
    int cc = (tid % 16) * 4;   // s (scores) / h (output) col block
    float m_i[4], l_i[4], oacc[4][4];
    #pragma unroll
    for (int i = 0; i < 4; i++) {
        m_i[i] = -3.0e38f; l_i[i] = 0.f;
        #pragma unroll
        for (int j = 0; j < 4; j++) oacc[i][j] = 0.f;
    }
    float padQ[4];
    #pragma unroll
    for (int i = 0; i < 4; i++) padQ[i] = pad[b*1024 + qt*64 + rr + i];

    for (int st = 0; st <= qt; st++) {
        __syncthreads();  // previous-iteration KP/Vs reads done
        {   // load K (transposed) and V tiles
            int s = tid / 4, seg = tid % 4;
            const float* kp = k + base + (long)(st*64 + s) * DDIM + seg*16;
            const float* vp = v + base + (long)(st*64 + s) * DDIM + seg*16;
            #pragma unroll
            for (int u = 0; u < 4; u++) {
                float4 t4 = *(const float4*)(kp + u*4);
                int h = seg*16 + u*4;
                KP[(h+0)*64 + s] = t4.x; KP[(h+1)*64 + s] = t4.y;
                KP[(h+2)*64 + s] = t4.z; KP[(h+3)*64 + s] = t4.w;
                float4 v4 = *(const float4*)(vp + u*4);
                *(float4*)&Vs[s*64 + seg*16 + u*4] = v4;
            }
        }
        __syncthreads();
        // scores: sc[i][j] = q[rr+i] . k[cc+j]
        float sc[4][4];
        #pragma unroll
        for (int i = 0; i < 4; i++)
            #pragma unroll
            for (int j = 0; j < 4; j++) sc[i][j] = 0.f;
        #pragma unroll 16
        for (int h = 0; h < 64; h++) {
            float4 qv = *(const float4*)(QsT + h*64 + rr);
            float4 kv = *(const float4*)(KP  + h*64 + cc);
            float qa[4] = {qv.x, qv.y, qv.z, qv.w};
            float kb[4] = {kv.x, kv.y, kv.z, kv.w};
            #pragma unroll
            for (int i = 0; i < 4; i++)
                #pragma unroll
                for (int j = 0; j < 4; j++)
                    sc[i][j] += qa[i] * kb[j];
        }
        // mask (causal + padding), reference-literal -1e9
        float padK[4];
        #pragma unroll
        for (int j = 0; j < 4; j++) padK[j] = pad[b*1024 + st*64 + cc + j];
        #pragma unroll
        for (int i = 0; i < 4; i++) {
            int tg = qt*64 + rr + i;
            #pragma unroll
            for (int j = 0; j < 4; j++) {
                int sg = st*64 + cc + j;
                bool valid = (sg <= tg) && (padQ[i] != 0.f) && (padK[j] != 0.f);
                if (!valid) sc[i][j] = -1e9f;
            }
        }
        __syncthreads();  // all KP (K) reads done before overwriting with P
        // online softmax per row
        #pragma unroll
        for (int i = 0; i < 4; i++) {
            float mx = fmaxf(fmaxf(sc[i][0], sc[i][1]), fmaxf(sc[i][2], sc[i][3]));
            #pragma unroll
            for (int off = 8; off >= 1; off >>= 1)
                mx = fmaxf(mx, __shfl_xor_sync(0xffffffffu, mx, off, 16));
            float mnew = fmaxf(m_i[i], mx);
            float corr = __expf(m_i[i] - mnew);
            l_i[i] *= corr;
            #pragma unroll
            for (int j = 0; j < 4; j++) oacc[i][j] *= corr;
            float rs = 0.f;
            #pragma unroll
            for (int j = 0; j < 4; j++) {
                float p = __expf(sc[i][j] - mnew);
                sc[i][j] = p; rs += p;
            }
            #pragma unroll
            for (int off = 8; off >= 1; off >>= 1)
                rs += __shfl_xor_sync(0xffffffffu, rs, off, 16);
            l_i[i] += rs; m_i[i] = mnew;
            #pragma unroll
            for (int j = 0; j < 4; j++)
                KP[(cc+j)*64 + rr + i] = sc[i][j];   // P[s][r]
        }
        __syncthreads();
        // O += P @ V
        #pragma unroll 8
        for (int s = 0; s < 64; s++) {
            float4 pv = *(const float4*)(KP + s*64 + rr);
            float4 vv = *(const float4*)(Vs + s*64 + cc);
            float pa[4] = {pv.x, pv.y, pv.z, pv.w};
            float vb[4] = {vv.x, vv.y, vv.z, vv.w};
            #pragma unroll
            for (int i = 0; i < 4; i++)
                #pragma unroll
                for (int j = 0; j < 4; j++)
                    oacc[i][j] += pa[i] * vb[j];
        }
    }
    // write O / l
    #pragma unroll
    for (int i = 0; i < 4; i++) {
        float inv = 1.0f / l_i[i];
        float4 r4 = make_float4(oacc[i][0]*inv, oacc[i][1]*inv,
                                oacc[i][2]*inv, oacc[i][3]*inv);
        *(float4*)(out + base + (long)(qt*64 + rr + i) * DDIM + cc) = r4;
    }
}

// ---------------- host ----------------
extern "C" void kernel_launch(void* const* d_in, const int* in_sizes, int n_in,
                              void* d_out, int out_size) {
    const float* x    = (const float*)d_in[0];
    const float* padding = (const float*)d_in[1];
    const float* rms_scale = (const float*)d_in[2];
    const float* pds  = (const float*)d_in[3];
    const float* wq   = (const float*)d_in[4];
    const float* bq   = (const float*)d_in[5];
    const float* wk   = (const float*)d_in[6];
    const float* bk   = (const float*)d_in[7];
    const float* wv   = (const float*)d_in[8];
    const float* bv   = (const float*)d_in[9];
    const float* wo   = (const float*)d_in[10];
    const float* bo   = (const float*)d_in[11];
    const float* lng  = (const float*)d_in[12];
    const float* lnb  = (const float*)d_in[13];
    const float* w1   = (const float*)d_in[14];
    const float* b1   = (const float*)d_in[15];
    const float* w2   = (const float*)d_in[16];
    const float* b2   = (const float*)d_in[17];
    float* out = (float*)d_out;

    int M = in_sizes[0] / DDIM;   // B*T = 8192
    int B = M / 1024;

    float *p_xn, *p_q, *p_k, *p_v, *p_ao, *p_attn, *p_h1, *p_wot, *p_qs;
    cudaGetSymbolAddress((void**)&p_xn,  g_xn);
    cudaGetSymbolAddress((void**)&p_q,   g_q);
    cudaGetSymbolAddress((void**)&p_k,   g_k);
    cudaGetSymbolAddress((void**)&p_v,   g_v);
    cudaGetSymbolAddress((void**)&p_ao,  g_ao);
    cudaGetSymbolAddress((void**)&p_attn,g_attn);
    cudaGetSymbolAddress((void**)&p_h1,  g_h1);
    cudaGetSymbolAddress((void**)&p_wot, g_wot);
    cudaGetSymbolAddress((void**)&p_qs,  g_qs);

    qscale_kernel<<<1, 64>>>(pds, p_qs);
    rmsnorm_kernel<<<M, 256>>>(x, rms_scale, p_xn);

    dim3 g1(DDIM/128, M/128);
    sgemm128<<<g1, 256>>>(p_xn, wq, bq, nullptr, p_qs, p_q, M, DDIM, DDIM, 1);
    sgemm128<<<g1, 256>>>(p_xn, wk, bk, nullptr, nullptr, p_k, M, DDIM, DDIM, 0);
    sgemm128<<<g1, 256>>>(p_xn, wv, bv, nullptr, nullptr, p_v, M, DDIM, DDIM, 0);

    transpose1024<<<dim3(32, 32), dim3(32, 8)>>>(wo, p_wot);

    attn_kernel<<<dim3(16, 16, B), 256>>>(p_q, p_k, p_v, padding, p_ao);

    sgemm128<<<g1, 256>>>(p_ao, p_wot, bo, x, nullptr, p_attn, M, DDIM, DDIM, 3);

    layernorm_kernel<<<M, 256>>>(p_attn, lng, lnb, p_xn);

    dim3 g2(FDIM/128, M/128);
    sgemm128<<<g2, 256>>>(p_xn, w1, b1, nullptr, nullptr, p_h1, M, FDIM, DDIM, 2);
    sgemm128<<<g1, 256>>>(p_h1, w2, b2, p_attn, nullptr, out, M, DDIM, FDIM, 3);
}

// round 3
// speedup vs baseline: 2.0814x; 2.0814x over previous
#include <cuda_runtime.h>
#include <cstdint>
#include <math.h>

#define MROWS 8192
#define DDIM  1024
#define FDIM  4096
#define QS3   3072

// ---------------- scratch (static device globals; no allocations) ----------
__device__ float g_xn  [MROWS*DDIM];
__device__ float g_qkv [MROWS*QS3];
__device__ float g_ao  [MROWS*DDIM];
__device__ float g_attn[MROWS*DDIM];
__device__ float g_h1  [MROWS*FDIM];
__device__ float g_wt  [QS3*DDIM];      // qkv weights^T (tf32, q-scaled)
__device__ float g_w1t [FDIM*DDIM];
__device__ float g_w2t [DDIM*FDIM];
__device__ float g_wot [DDIM*DDIM];
__device__ float g_bqkv[QS3];
__device__ float g_qs  [64];

// ---------------- helpers ----------------
__device__ __forceinline__ float tf32r(float x) {
    uint32_t u; asm("cvt.rna.tf32.f32 %0, %1;" : "=r"(u) : "f"(x));
    return __uint_as_float(u);
}
__device__ __forceinline__ uint32_t smem_u32(const void* p) {
    uint32_t a;
    asm("{ .reg .u64 t; cvta.to.shared.u64 t, %1; cvt.u32.u64 %0, t; }" : "=r"(a) : "l"(p));
    return a;
}
__device__ __forceinline__ void cp16(uint32_t dst, const void* src) {
    asm volatile("cp.async.cg.shared.global [%0], [%1], 16;" :: "r"(dst), "l"(src));
}
__device__ __forceinline__ void mma16n8k8(float c[4],
        uint32_t a0, uint32_t a1, uint32_t a2, uint32_t a3,
        uint32_t b0, uint32_t b1) {
    asm volatile("mma.sync.aligned.m16n8k8.row.col.f32.tf32.tf32.f32 "
        "{%0,%1,%2,%3}, {%4,%5,%6,%7}, {%8,%9}, {%0,%1,%2,%3};"
        : "+f"(c[0]), "+f"(c[1]), "+f"(c[2]), "+f"(c[3])
        : "r"(a0), "r"(a1), "r"(a2), "r"(a3), "r"(b0), "r"(b1));
}

// ---------------- tf32 mma.sync GEMM: C[M,Nc] = A[M,K] @ B'[Nc,K]^T -------
// CTA 128x128, BK=32, 256 threads, double-buffered cp.async.
// mode 0: +bias   mode 2: relu(+bias)->tf32 round   mode 3: +bias+Res
#define BM 128
#define BN 128
#define BK 32
#define LDS_PITCH 36                       // 32 + 4 pad floats
#define STAGE_F (2 * BM * LDS_PITCH)       // A + B floats per stage
#define GSMEM (2 * STAGE_F * 4)            // bytes, 2 stages

__global__ __launch_bounds__(256)
void tgemm(const float* __restrict__ A, const float* __restrict__ B,
           const float* __restrict__ bias, const float* __restrict__ Res,
           float* __restrict__ C, int M, int Nc, int K, int mode) {
    extern __shared__ float sm[];
    int tid = threadIdx.x, lane = tid & 31, wid = tid >> 5;
    int gid = lane >> 2, tig = lane & 3;
    int warp_m = wid >> 2, warp_n = wid & 3;
    int m0 = warp_m * 64, n0 = warp_n * 32;

    size_t row0 = (size_t)blockIdx.y * BM, col0 = (size_t)blockIdx.x * BN;

    // loader indices: thread -> (row, 16B chunk group)
    int trow = tid >> 1;
    int kbase = (tid & 1) * 16;
    const float* gA = A + (row0 + trow) * (size_t)K + kbase;
    const float* gB = B + (col0 + trow) * (size_t)K + kbase;
    uint32_t sA = smem_u32(sm);
    uint32_t dstA = sA + (uint32_t)(trow * LDS_PITCH + kbase) * 4;
    uint32_t dstB = dstA + (uint32_t)(BM * LDS_PITCH) * 4;

    auto load_stage = [&](int s, int kt) {
        uint32_t so = (uint32_t)(s * STAGE_F) * 4;
        #pragma unroll
        for (int u = 0; u < 4; u++) {
            cp16(dstA + so + u * 16, gA + kt + u * 4);
            cp16(dstB + so + u * 16, gB + kt + u * 4);
        }
        asm volatile("cp.async.commit_group;");
    };

    float cfr[4][4][4];
    #pragma unroll
    for (int i = 0; i < 4; i++)
        #pragma unroll
        for (int j = 0; j < 4; j++)
            #pragma unroll
            for (int q = 0; q < 4; q++) cfr[i][j][q] = 0.f;

    int nk = K / BK;
    load_stage(0, 0);

    for (int it = 0; it < nk; ++it) {
        int s = it & 1;
        if (it + 1 < nk) {
            load_stage(s ^ 1, (it + 1) * BK);
            asm volatile("cp.async.wait_group 1;");
        } else {
            asm volatile("cp.async.wait_group 0;");
        }
        __syncthreads();

        const uint32_t* As = (const uint32_t*)(sm + s * STAGE_F);
        const uint32_t* Bs = As + BM * LDS_PITCH;
        #pragma unroll
        for (int kk = 0; kk < 4; kk++) {
            int kb = kk * 8;
            uint32_t af[4][4], bf[4][2];
            #pragma unroll
            for (int tm = 0; tm < 4; tm++) {
                int mr = m0 + tm * 16 + gid;
                af[tm][0] = As[mr * LDS_PITCH + kb + tig];
                af[tm][1] = As[(mr + 8) * LDS_PITCH + kb + tig];
                af[tm][2] = As[mr * LDS_PITCH + kb + tig + 4];
                af[tm][3] = As[(mr + 8) * LDS_PITCH + kb + tig + 4];
            }
            #pragma unroll
            for (int tn = 0; tn < 4; tn++) {
                int nr = n0 + tn * 8 + gid;
                bf[tn][0] = Bs[nr * LDS_PITCH + kb + tig];
                bf[tn][1] = Bs[nr * LDS_PITCH + kb + tig + 4];
            }
            #pragma unroll
            for (int tm = 0; tm < 4; tm++)
                #pragma unroll
                for (int tn = 0; tn < 4; tn++)
                    mma16n8k8(cfr[tm][tn],
                              af[tm][0], af[tm][1], af[tm][2], af[tm][3],
                              bf[tn][0], bf[tn][1]);
        }
        __syncthreads();
    }

    // epilogue
    #pragma unroll
    for (int tm = 0; tm < 4; tm++) {
        size_t ra = row0 + m0 + tm * 16 + gid;
        #pragma unroll
        for (int half = 0; half < 2; half++) {
            size_t row = ra + half * 8;
            float* crow = C + row * (size_t)Nc;
            const float* rrow = (mode == 3) ? (Res + row * (size_t)Nc) : nullptr;
            #pragma unroll
            for (int tn = 0; tn < 4; tn++) {
                size_t col = col0 + n0 + tn * 8 + 2 * tig;
                float v0 = cfr[tm][tn][half * 2 + 0] + bias[col];
                float v1 = cfr[tm][tn][half * 2 + 1] + bias[col + 1];
                if (mode == 2) {
                    v0 = tf32r(fmaxf(v0, 0.f));
                    v1 = tf32r(fmaxf(v1, 0.f));
                } else if (mode == 3) {
                    v0 += rrow[col];
                    v1 += rrow[col + 1];
                }
                *(float2*)(crow + col) = make_float2(v0, v1);
            }
        }
    }
}

// ---------------- per-dim q scale: (log2e/sqrt(H)) * softplus(p) ----------
__global__ void qscale_kernel(const float* __restrict__ p, float* __restrict__ s) {
    int h = threadIdx.x;
    if (h < 64) {
        float x  = p[h];
        float sp = (x > 20.f) ? x : log1pf(expf(x));
        s[h] = (1.442695041f / 8.0f) * sp;
    }
}

// ---------------- transpose + tf32 round (+ optional per-outrow scale) ----
__global__ void transpose_round(const float* __restrict__ in, float* __restrict__ out,
                                int R, int C, const float* __restrict__ scale) {
    __shared__ float t[32][33];
    int bx = blockIdx.x * 32, by = blockIdx.y * 32;
    int tx = threadIdx.x, ty = threadIdx.y;  // 32 x 8
    #pragma unroll
    for (int i = 0; i < 32; i += 8)
        t[ty + i][tx] = in[(size_t)(by + ty + i) * C + bx + tx];
    __syncthreads();
    #pragma unroll
    for (int i = 0; i < 32; i += 8) {
        int oc = bx + ty + i;
        float v = t[tx][ty + i];
        if (scale) v *= scale[oc & 63];
        out[(size_t)oc * R + by + tx] = tf32r(v);
    }
}

__global__ void round_copy(const float* __restrict__ in, float* __restrict__ out, int n) {
    int i = blockIdx.x * 256 + threadIdx.x;
    if (i < n) out[i] = tf32r(in[i]);
}

__global__ void bias_qkv(const float* __restrict__ bq, const float* __restrict__ bk,
                         const float* __restrict__ bv, const float* __restrict__ s,
                         float* __restrict__ out) {
    int i = blockIdx.x * 256 + threadIdx.x;
    if (i < 1024)      out[i] = bq[i] * s[i & 63];
    else if (i < 2048) out[i] = bk[i - 1024];
    else if (i < 3072) out[i] = bv[i - 2048];
}

// ---------------- RMSNorm (tf32-rounded output) ----------
__global__ void rmsnorm_kernel(const float* __restrict__ x,
                               const float* __restrict__ scale,
                               float* __restrict__ y) {
    int row = blockIdx.x, tid = threadIdx.x;
    const float4* xr = (const float4*)(x + (size_t)row * DDIM);
    float4 xv = xr[tid];
    float ss = xv.x*xv.x + xv.y*xv.y + xv.z*xv.z + xv.w*xv.w;
    __shared__ float red[256];
    red[tid] = ss; __syncthreads();
    for (int o = 128; o > 0; o >>= 1) {
        if (tid < o) red[tid] += red[tid + o];
        __syncthreads();
    }
    float inv = rsqrtf(red[0] * (1.0f / DDIM) + 1e-6f);
    float4 sv = ((const float4*)scale)[tid];
    float4 r;
    r.x = tf32r(xv.x * inv * sv.x); r.y = tf32r(xv.y * inv * sv.y);
    r.z = tf32r(xv.z * inv * sv.z); r.w = tf32r(xv.w * inv * sv.w);
    ((float4*)(y + (size_t)row * DDIM))[tid] = r;
}

// ---------------- LayerNorm (tf32-rounded output) ----------
__global__ void layernorm_kernel(const float* __restrict__ x,
                                 const float* __restrict__ gamma,
                                 const float* __restrict__ beta,
                                 float* __restrict__ y) {
    int row = blockIdx.x, tid = threadIdx.x;
    const float4* xr = (const float4*)(x + (size_t)row * DDIM);
    float4 xv = xr[tid];
    float s1 = xv.x + xv.y + xv.z + xv.w;
    float s2 = xv.x*xv.x + xv.y*xv.y + xv.z*xv.z + xv.w*xv.w;
    __shared__ float r1[256], r2[256];
    r1[tid] = s1; r2[tid] = s2; __syncthreads();
    for (int o = 128; o > 0; o >>= 1) {
        if (tid < o) { r1[tid] += r1[tid + o]; r2[tid] += r2[tid + o]; }
        __syncthreads();
    }
    float mean = r1[0] * (1.0f / DDIM);
    float var  = r2[0] * (1.0f / DDIM) - mean * mean;
    float inv  = rsqrtf(var + 1e-5f);
    float4 gv = ((const float4*)gamma)[tid];
    float4 bv = ((const float4*)beta)[tid];
    float4 r;
    r.x = tf32r((xv.x - mean) * inv * gv.x + bv.x);
    r.y = tf32r((xv.y - mean) * inv * gv.y + bv.y);
    r.z = tf32r((xv.z - mean) * inv * gv.z + bv.z);
    r.w = tf32r((xv.w - mean) * inv * gv.w + bv.w);
    ((float4*)(y + (size_t)row * DDIM))[tid] = r;
}

// ---------------- causal flash attention (qkv packed, stride 3072) --------
__global__ __launch_bounds__(256)
void attn_kernel(const float* __restrict__ qkv, const float* __restrict__ pad,
                 float* __restrict__ out) {
    __shared__ float QsT[64*64];   // [h][r]
    __shared__ float KP [64*64];   // [h][s] for K, reused as P[s][r]
    __shared__ float Vs [64*64];   // [s][c]
    int tid = threadIdx.x;
    int qt = blockIdx.x, n = blockIdx.y, b = blockIdx.z;
    size_t qbase = (size_t)b * 1024 * QS3 + n * 64;

    {
        int r = tid / 4, seg = tid % 4;
        const float* qp = qkv + qbase + (size_t)(qt*64 + r) * QS3 + seg*16;
        #pragma unroll
        for (int u = 0; u < 4; u++) {
            float4 t4 = *(const float4*)(qp + u*4);
            int h = seg*16 + u*4;
            QsT[(h+0)*64 + r] = t4.x; QsT[(h+1)*64 + r] = t4.y;
            QsT[(h+2)*64 + r] = t4.z; QsT[(h+3)*64 + r] = t4.w;
        }
    }
    int rr = (tid / 16) * 4;
    int cc = (tid % 16) * 4;
    float m_i[4], l_i[4], oacc[4][4];
    #pragma unroll
    for (int i = 0; i < 4; i++) {
        m_i[i] = -3.0e38f; l_i[i] = 0.f;
        #pragma unroll
        for (int j = 0; j < 4; j++) oacc[i][j] = 0.f;
    }
    float padQ[4];
    #pragma unroll
    for (int i = 0; i < 4; i++) padQ[i] = pad[b*1024 + qt*64 + rr + i];

    for (int st = 0; st <= qt; st++) {
        __syncthreads();
        {
            int s = tid / 4, seg = tid % 4;
            const float* kp = qkv + qbase + (size_t)(st*64 + s) * QS3 + 1024 + seg*16;
            const float* vp = qkv + qbase + (size_t)(st*64 + s) * QS3 + 2048 + seg*16;
            #pragma unroll
            for (int u = 0; u < 4; u++) {
                float4 t4 = *(const float4*)(kp + u*4);
                int h = seg*16 + u*4;
                KP[(h+0)*64 + s] = t4.x; KP[(h+1)*64 + s] = t4.y;
                KP[(h+2)*64 + s] = t4.z; KP[(h+3)*64 + s] = t4.w;
                float4 v4 = *(const float4*)(vp + u*4);
                *(float4*)&Vs[s*64 + seg*16 + u*4] = v4;
            }
        }
        __syncthreads();
        float sc[4][4];
        #pragma unroll
        for (int i = 0; i < 4; i++)
            #pragma unroll
            for (int j = 0; j < 4; j++) sc[i][j] = 0.f;
        #pragma unroll 16
        for (int h = 0; h < 64; h++) {
            float4 qv = *(const float4*)(QsT + h*64 + rr);
            float4 kv = *(const float4*)(KP  + h*64 + cc);
            float qa[4] = {qv.x, qv.y, qv.z, qv.w};
            float kb[4] = {kv.x, kv.y, kv.z, kv.w};
            #pragma unroll
            for (int i = 0; i < 4; i++)
                #pragma unroll
                for (int j = 0; j < 4; j++)
                    sc[i][j] += qa[i] * kb[j];
        }
        float padK[4];
        #pragma unroll
        for (int j = 0; j < 4; j++) padK[j] = pad[b*1024 + st*64 + cc + j];
        #pragma unroll
        for (int i = 0; i < 4; i++) {
            int tg = qt*64 + rr + i;
            #pragma unroll
            for (int j = 0; j < 4; j++) {
                int sg = st*64 + cc + j;
                bool valid = (sg <= tg) && (padQ[i] != 0.f) && (padK[j] != 0.f);
                if (!valid) sc[i][j] = -1e9f;
            }
        }
        __syncthreads();
        #pragma unroll
        for (int i = 0; i < 4; i++) {
            float mx = fmaxf(fmaxf(sc[i][0], sc[i][1]), fmaxf(sc[i][2], sc[i][3]));
            #pragma unroll
            for (int off = 8; off >= 1; off >>= 1)
                mx = fmaxf(mx, __shfl_xor_sync(0xffffffffu, mx, off, 16));
            float mnew = fmaxf(m_i[i], mx);
            float corr = __expf(m_i[i] - mnew);
            l_i[i] *= corr;
            #pragma unroll
            for (int j = 0; j < 4; j++) oacc[i][j] *= corr;
            float rs = 0.f;
            #pragma unroll
            for (int j = 0; j < 4; j++) {
                float p = __expf(sc[i][j] - mnew);
                sc[i][j] = p; rs += p;
            }
            #pragma unroll
            for (int off = 8; off >= 1; off >>= 1)
                rs += __shfl_xor_sync(0xffffffffu, rs, off, 16);
            l_i[i] += rs; m_i[i] = mnew;
            #pragma unroll
            for (int j = 0; j < 4; j++)
                KP[(cc+j)*64 + rr + i] = sc[i][j];
        }
        __syncthreads();
        #pragma unroll 8
        for (int s = 0; s < 64; s++) {
            float4 pv = *(const float4*)(KP + s*64 + rr);
            float4 vv = *(const float4*)(Vs + s*64 + cc);
            float pa[4] = {pv.x, pv.y, pv.z, pv.w};
            float vb[4] = {vv.x, vv.y, vv.z, vv.w};
            #pragma unroll
            for (int i = 0; i < 4; i++)
                #pragma unroll
                for (int j = 0; j < 4; j++)
                    oacc[i][j] += pa[i] * vb[j];
        }
    }
    size_t obase = (size_t)b * 1024 * DDIM + n * 64;
    #pragma unroll
    for (int i = 0; i < 4; i++) {
        float inv = 1.0f / l_i[i];
        float4 r4 = make_float4(tf32r(oacc[i][0]*inv), tf32r(oacc[i][1]*inv),
                                tf32r(oacc[i][2]*inv), tf32r(oacc[i][3]*inv));
        *(float4*)(out + obase + (size_t)(qt*64 + rr + i) * DDIM + cc) = r4;
    }
}

// ---------------- host ----------------
extern "C" void kernel_launch(void* const* d_in, const int* in_sizes, int n_in,
                              void* d_out, int out_size) {
    const float* x    = (const float*)d_in[0];
    const float* padding = (const float*)d_in[1];
    const float* rms_scale = (const float*)d_in[2];
    const float* pds  = (const float*)d_in[3];
    const float* wq   = (const float*)d_in[4];
    const float* bq   = (const float*)d_in[5];
    const float* wk   = (const float*)d_in[6];
    const float* bk   = (const float*)d_in[7];
    const float* wv   = (const float*)d_in[8];
    const float* bv   = (const float*)d_in[9];
    const float* wo   = (const float*)d_in[10];
    const float* bo   = (const float*)d_in[11];
    const float* lng  = (const float*)d_in[12];
    const float* lnb  = (const float*)d_in[13];
    const float* w1   = (const float*)d_in[14];
    const float* b1   = (const float*)d_in[15];
    const float* w2   = (const float*)d_in[16];
    const float* b2   = (const float*)d_in[17];
    float* out = (float*)d_out;

    int M = in_sizes[0] / DDIM;   // 8192
    int B = M / 1024;

    float *p_xn, *p_qkv, *p_ao, *p_attn, *p_h1, *p_wt, *p_w1t, *p_w2t, *p_wot, *p_bqkv, *p_qs;
    cudaGetSymbolAddress((void**)&p_xn,  g_xn);
    cudaGetSymbolAddress((void**)&p_qkv, g_qkv);
    cudaGetSymbolAddress((void**)&p_ao,  g_ao);
    cudaGetSymbolAddress((void**)&p_attn,g_attn);
    cudaGetSymbolAddress((void**)&p_h1,  g_h1);
    cudaGetSymbolAddress((void**)&p_wt,  g_wt);
    cudaGetSymbolAddress((void**)&p_w1t, g_w1t);
    cudaGetSymbolAddress((void**)&p_w2t, g_w2t);
    cudaGetSymbolAddress((void**)&p_wot, g_wot);
    cudaGetSymbolAddress((void**)&p_bqkv,g_bqkv);
    cudaGetSymbolAddress((void**)&p_qs,  g_qs);

    cudaFuncSetAttribute(tgemm, cudaFuncAttributeMaxDynamicSharedMemorySize, GSMEM);

    // weight prep
    qscale_kernel<<<1, 64>>>(pds, p_qs);
    dim3 tb(32, 8);
    transpose_round<<<dim3(32, 32), tb>>>(wq, p_wt,               1024, 1024, p_qs);
    transpose_round<<<dim3(32, 32), tb>>>(wk, p_wt + 1024*1024,   1024, 1024, nullptr);
    transpose_round<<<dim3(32, 32), tb>>>(wv, p_wt + 2*1024*1024, 1024, 1024, nullptr);
    transpose_round<<<dim3(128, 32), tb>>>(w1, p_w1t, 1024, 4096, nullptr);
    transpose_round<<<dim3(32, 128), tb>>>(w2, p_w2t, 4096, 1024, nullptr);
    round_copy<<<4096, 256>>>(wo, p_wot, 1024*1024);
    bias_qkv<<<12, 256>>>(bq, bk, bv, p_qs, p_bqkv);

    // attention block
    rmsnorm_kernel<<<M, 256>>>(x, rms_scale, p_xn);
    tgemm<<<dim3(QS3/BN, M/BM), 256, GSMEM>>>(p_xn, p_wt, p_bqkv, nullptr, p_qkv, M, QS3, 1024, 0);
    attn_kernel<<<dim3(16, 16, B), 256>>>(p_qkv, padding, p_ao);
    tgemm<<<dim3(DDIM/BN, M/BM), 256, GSMEM>>>(p_ao, p_wot, bo, x, p_attn, M, DDIM, 1024, 3);

    // FFN block
    layernorm_kernel<<<M, 256>>>(p_attn, lng, lnb, p_xn);
    tgemm<<<dim3(FDIM/BN, M/BM), 256, GSMEM>>>(p_xn, p_w1t, b1, nullptr, p_h1, M, FDIM, 1024, 2);
    tgemm<<<dim3(DDIM/BN, M/BM), 256, GSMEM>>>(p_h1, p_w2t, b2, p_attn, out, M, DDIM, 4096, 3);
}